// round 1
// baseline (speedup 1.0000x reference)
#include <cuda_runtime.h>
#include <math.h>
#include <float.h>

// ---------------------------------------------------------------------------
// ConvKAN3D: 3x [conv3d(3^3, pad1) -> spline(10 knots) + SiLU -> BN(eval) ->
// maxpool(2^3)] -> global mean -> fc1(relu) -> fc2
//
// Strategy: one fused kernel per block. Each thread computes ONE pooled output
// voxel: the 8 pre-pool conv results from a 4x4x4 input patch, then the
// pointwise chain and the max. CTILE=4 output channels per thread block to
// reuse input patches. Weights staged in shared memory.
// ---------------------------------------------------------------------------

// Scratch activations (device globals; no runtime allocation).
__device__ float g_s1[2u * 32u * 32u * 32u * 32u];   // [2,32,32,32,32]  8 MB
__device__ float g_s2[2u * 64u * 16u * 16u * 16u];   // [2,64,16,16,16]  2 MB
__device__ float g_s3[2u * 128u * 8u * 8u * 8u];     // [2,128,8,8,8]  0.5 MB

template<int CIN, int D, int CTILE>
__global__ void __launch_bounds__(256)
spline_block_kernel(const float* __restrict__ in,     // [2, CIN, D,D,D]
                    const float* __restrict__ cw,     // [COUT, CIN, 3,3,3]
                    const float* __restrict__ cb,     // [COUT]
                    const float* __restrict__ knots,  // [10]
                    const float* __restrict__ swp,    // [COUT, 10]
                    const float* __restrict__ w1p,    // [COUT]
                    const float* __restrict__ w2p,    // [COUT]
                    const float* __restrict__ gp,     // [COUT]
                    const float* __restrict__ bp,     // [COUT]
                    float* __restrict__ out,          // [2, COUT, (D/2)^3]
                    int COUT)
{
    constexpr int P  = D / 2;
    constexpr int NV = P * P * P;
    constexpr int NW = CTILE * CIN * 27;

    const int cobase = blockIdx.y * CTILE;
    const int b      = blockIdx.z;

    __shared__ float ws[NW];
    __shared__ float s_knots[10];
    __shared__ float s_sw[CTILE * 10];
    __shared__ float s_bias[CTILE], s_w1[CTILE], s_w2[CTILE],
                     s_scale[CTILE], s_beta[CTILE];

    // Stage weights / params
    for (int i = threadIdx.x; i < NW; i += blockDim.x)
        ws[i] = cw[(size_t)cobase * CIN * 27 + i];
    if (threadIdx.x < 10)
        s_knots[threadIdx.x] = knots[threadIdx.x];
    for (int i = threadIdx.x; i < CTILE * 10; i += blockDim.x)
        s_sw[i] = swp[cobase * 10 + i];
    if (threadIdx.x < CTILE) {
        int c = cobase + threadIdx.x;
        s_bias[threadIdx.x]  = cb[c];
        s_w1[threadIdx.x]    = w1p[c];
        s_w2[threadIdx.x]    = w2p[c];
        s_scale[threadIdx.x] = gp[c] * rsqrtf(1.0f + 1e-5f);
        s_beta[threadIdx.x]  = bp[c];
    }
    __syncthreads();

    const int vox = blockIdx.x * blockDim.x + threadIdx.x;
    if (vox >= NV) return;

    const int px = vox % P;
    const int py = (vox / P) % P;
    const int pz = vox / (P * P);
    const int x0 = 2 * px - 1;
    const int y0 = 2 * py - 1;
    const int z0 = 2 * pz - 1;

    float acc[CTILE][8];
    #pragma unroll
    for (int t = 0; t < CTILE; ++t)
        #pragma unroll
        for (int i = 0; i < 8; ++i)
            acc[t][i] = s_bias[t];

    const float* inb = in + (size_t)b * CIN * D * D * D;

    #pragma unroll 1
    for (int ci = 0; ci < CIN; ++ci) {
        const float* ip = inb + (size_t)ci * D * D * D;

        #pragma unroll
        for (int a = 0; a < 4; ++a) {              // input z-plane
            const int iz = z0 + a;
            const bool zv = (iz >= 0) && (iz < D);

            // load 4x4 plane with zero padding
            float p[16];
            #pragma unroll
            for (int r = 0; r < 4; ++r) {
                const int iy = y0 + r;
                const bool yv = zv && (iy >= 0) && (iy < D);
                const float* row = ip + ((size_t)(zv ? iz : 0) * D +
                                         (yv ? iy : 0)) * D;
                #pragma unroll
                for (int c = 0; c < 4; ++c) {
                    const int ix = x0 + c;
                    p[r * 4 + c] = (yv && ix >= 0 && ix < D)
                                     ? __ldg(row + ix) : 0.0f;
                }
            }

            // accumulate into the conv outputs this plane contributes to
            #pragma unroll
            for (int dz = 0; dz < 2; ++dz) {
                const int kd = a - dz;
                if (kd < 0 || kd > 2) continue;    // compile-time pruned
                #pragma unroll
                for (int t = 0; t < CTILE; ++t) {
                    const float* w = ws + (t * CIN + ci) * 27 + kd * 9;
                    #pragma unroll
                    for (int dy = 0; dy < 2; ++dy) {
                        #pragma unroll
                        for (int dx = 0; dx < 2; ++dx) {
                            float s = acc[t][dz * 4 + dy * 2 + dx];
                            #pragma unroll
                            for (int kh = 0; kh < 3; ++kh)
                                #pragma unroll
                                for (int kw = 0; kw < 3; ++kw)
                                    s = fmaf(p[(dy + kh) * 4 + dx + kw],
                                             w[kh * 3 + kw], s);
                            acc[t][dz * 4 + dy * 2 + dx] = s;
                        }
                    }
                }
            }
        }
    }

    // pointwise: spline + SiLU + BN(eval) + maxpool(2^3)
    #pragma unroll
    for (int t = 0; t < CTILE; ++t) {
        float mv = -FLT_MAX;
        #pragma unroll
        for (int i = 0; i < 8; ++i) {
            const float y = acc[t][i];
            float sp = 0.0f;
            #pragma unroll
            for (int k = 0; k < 10; ++k) {
                float u = fmaxf(y - s_knots[k], 0.0f);
                sp = fmaf(s_sw[t * 10 + k], u * u * u, sp);
            }
            const float sig = 1.0f / (1.0f + __expf(-y));
            float o = s_w1[t] * sp + s_w2[t] * (y * sig);
            o = fmaf(o, s_scale[t], s_beta[t]);
            mv = fmaxf(mv, o);
        }
        out[((size_t)(b * COUT + cobase + t)) * NV + vox] = mv;
    }
}

// mean over 512 spatial -> fc1(128->256, relu) -> fc2(256->2)
__global__ void __launch_bounds__(256)
head_kernel(const float* __restrict__ s3,      // [2,128,512]
            const float* __restrict__ fc1w,    // [256,128]
            const float* __restrict__ fc1b,    // [256]
            const float* __restrict__ fc2w,    // [2,256]
            const float* __restrict__ fc2b,    // [2]
            float* __restrict__ out)           // [2,2]
{
    const int b = blockIdx.x;
    const int t = threadIdx.x;

    __shared__ float mean[128];
    __shared__ float h[256];

    if (t < 128) {
        const float* p = s3 + ((size_t)b * 128 + t) * 512;
        float s = 0.0f;
        #pragma unroll 8
        for (int i = 0; i < 512; ++i) s += p[i];
        mean[t] = s * (1.0f / 512.0f);
    }
    __syncthreads();

    {
        float s = fc1b[t];
        const float* w = fc1w + t * 128;
        #pragma unroll 8
        for (int k = 0; k < 128; ++k) s = fmaf(mean[k], w[k], s);
        h[t] = fmaxf(s, 0.0f);
    }
    __syncthreads();

    if (t < 2) {
        float s = fc2b[t];
        const float* w = fc2w + t * 256;
        #pragma unroll 8
        for (int k = 0; k < 256; ++k) s = fmaf(h[k], w[k], s);
        out[b * 2 + t] = s;
    }
}

extern "C" void kernel_launch(void* const* d_in, const int* in_sizes, int n_in,
                              void* d_out, int out_size)
{
    (void)in_sizes; (void)n_in; (void)out_size;

    const float* x     = (const float*)d_in[0];
    const float* c1_w  = (const float*)d_in[1];
    const float* c1_b  = (const float*)d_in[2];
    const float* c1_k  = (const float*)d_in[3];
    const float* c1_sw = (const float*)d_in[4];
    const float* c1_w1 = (const float*)d_in[5];
    const float* c1_w2 = (const float*)d_in[6];
    const float* bn1_g = (const float*)d_in[7];
    const float* bn1_b = (const float*)d_in[8];
    const float* c2_w  = (const float*)d_in[9];
    const float* c2_b  = (const float*)d_in[10];
    const float* c2_k  = (const float*)d_in[11];
    const float* c2_sw = (const float*)d_in[12];
    const float* c2_w1 = (const float*)d_in[13];
    const float* c2_w2 = (const float*)d_in[14];
    const float* bn2_g = (const float*)d_in[15];
    const float* bn2_b = (const float*)d_in[16];
    const float* c3_w  = (const float*)d_in[17];
    const float* c3_b  = (const float*)d_in[18];
    const float* c3_k  = (const float*)d_in[19];
    const float* c3_sw = (const float*)d_in[20];
    const float* c3_w1 = (const float*)d_in[21];
    const float* c3_w2 = (const float*)d_in[22];
    const float* bn3_g = (const float*)d_in[23];
    const float* bn3_b = (const float*)d_in[24];
    const float* fc1_w = (const float*)d_in[25];
    const float* fc1_b = (const float*)d_in[26];
    const float* fc2_w = (const float*)d_in[27];
    const float* fc2_b = (const float*)d_in[28];
    float* out = (float*)d_out;

    float *s1, *s2, *s3;
    cudaGetSymbolAddress((void**)&s1, g_s1);
    cudaGetSymbolAddress((void**)&s2, g_s2);
    cudaGetSymbolAddress((void**)&s3, g_s3);

    // Block 1: CIN=1, D=64, COUT=32, CTILE=4 -> pooled 32^3
    {
        dim3 grid(32768 / 256, 32 / 4, 2);
        spline_block_kernel<1, 64, 4><<<grid, 256>>>(
            x, c1_w, c1_b, c1_k, c1_sw, c1_w1, c1_w2, bn1_g, bn1_b, s1, 32);
    }
    // Block 2: CIN=32, D=32, COUT=64, CTILE=4 -> pooled 16^3
    {
        dim3 grid(4096 / 256, 64 / 4, 2);
        spline_block_kernel<32, 32, 4><<<grid, 256>>>(
            s1, c2_w, c2_b, c2_k, c2_sw, c2_w1, c2_w2, bn2_g, bn2_b, s2, 64);
    }
    // Block 3: CIN=64, D=16, COUT=128, CTILE=4 -> pooled 8^3
    {
        dim3 grid(512 / 256, 128 / 4, 2);
        spline_block_kernel<64, 16, 4><<<grid, 256>>>(
            s2, c3_w, c3_b, c3_k, c3_sw, c3_w1, c3_w2, bn3_g, bn3_b, s3, 128);
    }
    // Head
    head_kernel<<<2, 256>>>(s3, fc1_w, fc1_b, fc2_w, fc2_b, out);
}

// round 2
// speedup vs baseline: 1.1803x; 1.1803x over previous
#include <cuda_runtime.h>
#include <math.h>
#include <float.h>

// ---------------------------------------------------------------------------
// ConvKAN3D fused pipeline.
// R1 changes vs R0:
//  - spline evaluated as precomputed piecewise cubic (11 segments/channel)
//  - CTILE=8 for block2 (dominant FMA kernel)
//  - head split: wide mean-reduction kernel (grid=256) + tiny FC kernel
// ---------------------------------------------------------------------------

// Scratch activations (device globals; no runtime allocation).
__device__ float  g_s1[2u * 32u * 32u * 32u * 32u];   // 8 MB
__device__ float  g_s2[2u * 64u * 16u * 16u * 16u];   // 2 MB
__device__ float  g_s3[2u * 128u * 8u * 8u * 8u];     // 0.5 MB
__device__ float4 g_coef[224 * 11];                   // piecewise-cubic coeffs
__device__ float  g_mean[2 * 128];

// --- Precompute piecewise cubic coefficients for all 3 layers -------------
// sum_k sw_k * relu(y - t_k)^3, segment e has knots 0..e-1 active.
// (y-t)^3 = y^3 - 3t y^2 + 3t^2 y - t^3  -> (a0,a1,a2,a3) prefix sums.
__global__ void coef_kernel(const float* __restrict__ k1, const float* __restrict__ sw1,
                            const float* __restrict__ k2, const float* __restrict__ sw2,
                            const float* __restrict__ k3, const float* __restrict__ sw3)
{
    const int t = threadIdx.x;            // 0..223 global channel id
    if (t >= 224) return;
    const float* kn; const float* sw;
    if (t < 32)       { kn = k1; sw = sw1 + t * 10; }
    else if (t < 96)  { kn = k2; sw = sw2 + (t - 32) * 10; }
    else              { kn = k3; sw = sw3 + (t - 96) * 10; }

    float4 a = make_float4(0.f, 0.f, 0.f, 0.f);
    g_coef[t * 11 + 0] = a;
    for (int e = 1; e <= 10; ++e) {
        const float tk = kn[e - 1];
        const float s  = sw[e - 1];
        a.x = fmaf(-s * tk * tk, tk, a.x);   // -s t^3
        a.y = fmaf(3.f * s * tk, tk, a.y);   // +3 s t^2
        a.z = fmaf(-3.f * s, tk, a.z);       // -3 s t
        a.w += s;                            // +s
        g_coef[t * 11 + e] = a;
    }
}

// --- Fused conv3d + spline + SiLU + BN(eval) + maxpool ---------------------
template<int CIN, int D, int CTILE>
__global__ void __launch_bounds__(256)
spline_block_kernel(const float* __restrict__ in,     // [2, CIN, D,D,D]
                    const float* __restrict__ cw,     // [COUT, CIN, 27]
                    const float* __restrict__ cb,     // [COUT]
                    const float* __restrict__ w1p,
                    const float* __restrict__ w2p,
                    const float* __restrict__ gp,
                    const float* __restrict__ bp,
                    float* __restrict__ out,          // [2, COUT, (D/2)^3]
                    int COUT, int coefBase)
{
    constexpr int P  = D / 2;
    constexpr int NV = P * P * P;
    constexpr int NW = CTILE * CIN * 27;

    const int cobase = blockIdx.y * CTILE;
    const int b      = blockIdx.z;

    __shared__ float  ws[NW];
    __shared__ float4 s_coef[CTILE * 11];
    __shared__ float  s_bias[CTILE], s_w1[CTILE], s_w2[CTILE],
                      s_scale[CTILE], s_beta[CTILE];

    for (int i = threadIdx.x; i < NW; i += blockDim.x)
        ws[i] = cw[(size_t)cobase * CIN * 27 + i];
    for (int i = threadIdx.x; i < CTILE * 11; i += blockDim.x)
        s_coef[i] = g_coef[(coefBase + cobase) * 11 + i];
    if (threadIdx.x < CTILE) {
        int c = cobase + threadIdx.x;
        s_bias[threadIdx.x]  = cb[c];
        s_w1[threadIdx.x]    = w1p[c];
        s_w2[threadIdx.x]    = w2p[c];
        s_scale[threadIdx.x] = gp[c] * rsqrtf(1.0f + 1e-5f);
        s_beta[threadIdx.x]  = bp[c];
    }
    __syncthreads();

    const int vox = blockIdx.x * blockDim.x + threadIdx.x;
    if (vox >= NV) return;

    const int px = vox % P;
    const int py = (vox / P) % P;
    const int pz = vox / (P * P);
    const int x0 = 2 * px - 1;
    const int y0 = 2 * py - 1;
    const int z0 = 2 * pz - 1;

    float acc[CTILE][8];
    #pragma unroll
    for (int t = 0; t < CTILE; ++t)
        #pragma unroll
        for (int i = 0; i < 8; ++i)
            acc[t][i] = s_bias[t];

    const float* inb = in + (size_t)b * CIN * D * D * D;

    #pragma unroll 1
    for (int ci = 0; ci < CIN; ++ci) {
        const float* ip = inb + (size_t)ci * D * D * D;

        #pragma unroll
        for (int a = 0; a < 4; ++a) {              // input z-plane
            const int iz = z0 + a;
            const bool zv = (iz >= 0) && (iz < D);

            float p[16];
            #pragma unroll
            for (int r = 0; r < 4; ++r) {
                const int iy = y0 + r;
                const bool yv = zv && (iy >= 0) && (iy < D);
                const float* row = ip + ((size_t)(zv ? iz : 0) * D +
                                         (yv ? iy : 0)) * D;
                #pragma unroll
                for (int c = 0; c < 4; ++c) {
                    const int ix = x0 + c;
                    p[r * 4 + c] = (yv && ix >= 0 && ix < D)
                                     ? __ldg(row + ix) : 0.0f;
                }
            }

            #pragma unroll
            for (int dz = 0; dz < 2; ++dz) {
                const int kd = a - dz;
                if (kd < 0 || kd > 2) continue;    // compile-time pruned
                #pragma unroll
                for (int t = 0; t < CTILE; ++t) {
                    const float* w = ws + (t * CIN + ci) * 27 + kd * 9;
                    #pragma unroll
                    for (int dy = 0; dy < 2; ++dy) {
                        #pragma unroll
                        for (int dx = 0; dx < 2; ++dx) {
                            float s = acc[t][dz * 4 + dy * 2 + dx];
                            #pragma unroll
                            for (int kh = 0; kh < 3; ++kh)
                                #pragma unroll
                                for (int kw = 0; kw < 3; ++kw)
                                    s = fmaf(p[(dy + kh) * 4 + dx + kw],
                                             w[kh * 3 + kw], s);
                            acc[t][dz * 4 + dy * 2 + dx] = s;
                        }
                    }
                }
            }
        }
    }

    // pointwise: piecewise-cubic spline + SiLU + BN(eval) + maxpool(2^3)
    #pragma unroll
    for (int t = 0; t < CTILE; ++t) {
        float mv = -FLT_MAX;
        #pragma unroll
        for (int i = 0; i < 8; ++i) {
            const float y = acc[t][i];
            int e = __float2int_rd((y + 1.0f) * 4.5f) + 1;
            e = max(0, min(10, e));
            const float4 cf = s_coef[t * 11 + e];
            const float sp = fmaf(fmaf(fmaf(cf.w, y, cf.z), y, cf.y), y, cf.x);
            const float sig = 1.0f / (1.0f + __expf(-y));
            float o = s_w1[t] * sp + s_w2[t] * (y * sig);
            o = fmaf(o, s_scale[t], s_beta[t]);
            mv = fmaxf(mv, o);
        }
        out[((size_t)(b * COUT + cobase + t)) * NV + vox] = mv;
    }
}

// --- Head: mean over 512 spatial per (b,c) ---------------------------------
__global__ void __launch_bounds__(64)
mean_kernel(const float* __restrict__ s3)   // [2,128,512]
{
    const int bc = blockIdx.x;              // 0..255
    const int t  = threadIdx.x;             // 0..63
    const float* p = s3 + (size_t)bc * 512;

    float s = 0.0f;
    #pragma unroll
    for (int i = 0; i < 8; ++i) s += p[t + i * 64];

    // warp + block reduce (2 warps)
    #pragma unroll
    for (int off = 16; off > 0; off >>= 1)
        s += __shfl_down_sync(0xffffffffu, s, off);
    __shared__ float part[2];
    if ((t & 31) == 0) part[t >> 5] = s;
    __syncthreads();
    if (t == 0) g_mean[bc] = (part[0] + part[1]) * (1.0f / 512.0f);
}

// --- fc1(relu) -> fc2 -------------------------------------------------------
__global__ void __launch_bounds__(256)
fc_kernel(const float* __restrict__ fc1w,   // [256,128]
          const float* __restrict__ fc1b,
          const float* __restrict__ fc2w,   // [2,256]
          const float* __restrict__ fc2b,
          float* __restrict__ out)          // [2,2]
{
    const int t = threadIdx.x;
    __shared__ float m[2][128];
    __shared__ float h[2][256];

    if (t < 256) {
        // load means for both batches
        if (t < 128) { m[0][t] = g_mean[t]; m[1][t] = g_mean[128 + t]; }
    }
    __syncthreads();

    #pragma unroll
    for (int b = 0; b < 2; ++b) {
        float s = fc1b[t];
        const float* w = fc1w + t * 128;
        #pragma unroll 8
        for (int k = 0; k < 128; ++k) s = fmaf(m[b][k], w[k], s);
        h[b][t] = fmaxf(s, 0.0f);
    }
    __syncthreads();

    if (t < 4) {
        const int b = t >> 1, o = t & 1;
        float s = fc2b[o];
        const float* w = fc2w + o * 256;
        #pragma unroll 8
        for (int k = 0; k < 256; ++k) s = fmaf(h[b][k], w[k], s);
        out[b * 2 + o] = s;
    }
}

extern "C" void kernel_launch(void* const* d_in, const int* in_sizes, int n_in,
                              void* d_out, int out_size)
{
    (void)in_sizes; (void)n_in; (void)out_size;

    const float* x     = (const float*)d_in[0];
    const float* c1_w  = (const float*)d_in[1];
    const float* c1_b  = (const float*)d_in[2];
    const float* c1_k  = (const float*)d_in[3];
    const float* c1_sw = (const float*)d_in[4];
    const float* c1_w1 = (const float*)d_in[5];
    const float* c1_w2 = (const float*)d_in[6];
    const float* bn1_g = (const float*)d_in[7];
    const float* bn1_b = (const float*)d_in[8];
    const float* c2_w  = (const float*)d_in[9];
    const float* c2_b  = (const float*)d_in[10];
    const float* c2_k  = (const float*)d_in[11];
    const float* c2_sw = (const float*)d_in[12];
    const float* c2_w1 = (const float*)d_in[13];
    const float* c2_w2 = (const float*)d_in[14];
    const float* bn2_g = (const float*)d_in[15];
    const float* bn2_b = (const float*)d_in[16];
    const float* c3_w  = (const float*)d_in[17];
    const float* c3_b  = (const float*)d_in[18];
    const float* c3_k  = (const float*)d_in[19];
    const float* c3_sw = (const float*)d_in[20];
    const float* c3_w1 = (const float*)d_in[21];
    const float* c3_w2 = (const float*)d_in[22];
    const float* bn3_g = (const float*)d_in[23];
    const float* bn3_b = (const float*)d_in[24];
    const float* fc1_w = (const float*)d_in[25];
    const float* fc1_b = (const float*)d_in[26];
    const float* fc2_w = (const float*)d_in[27];
    const float* fc2_b = (const float*)d_in[28];
    float* out = (float*)d_out;

    float *s1, *s2, *s3;
    cudaGetSymbolAddress((void**)&s1, g_s1);
    cudaGetSymbolAddress((void**)&s2, g_s2);
    cudaGetSymbolAddress((void**)&s3, g_s3);

    coef_kernel<<<1, 224>>>(c1_k, c1_sw, c2_k, c2_sw, c3_k, c3_sw);

    // Block 1: CIN=1, D=64, COUT=32, CTILE=4
    {
        dim3 grid(32768 / 256, 32 / 4, 2);
        spline_block_kernel<1, 64, 4><<<grid, 256>>>(
            x, c1_w, c1_b, c1_w1, c1_w2, bn1_g, bn1_b, s1, 32, 0);
    }
    // Block 2: CIN=32, D=32, COUT=64, CTILE=8  (dominant FMA kernel)
    {
        dim3 grid(4096 / 256, 64 / 8, 2);
        spline_block_kernel<32, 32, 8><<<grid, 256>>>(
            s1, c2_w, c2_b, c2_w1, c2_w2, bn2_g, bn2_b, s2, 64, 32);
    }
    // Block 3: CIN=64, D=16, COUT=128, CTILE=4 (smem limit)
    {
        dim3 grid(512 / 256, 128 / 4, 2);
        spline_block_kernel<64, 16, 4><<<grid, 256>>>(
            s2, c3_w, c3_b, c3_w1, c3_w2, bn3_g, bn3_b, s3, 128, 96);
    }

    mean_kernel<<<256, 64>>>(s3);
    fc_kernel<<<1, 256>>>(fc1_w, fc1_b, fc2_w, fc2_b, out);
}

// round 3
// speedup vs baseline: 1.5875x; 1.3451x over previous
#include <cuda_runtime.h>
#include <math.h>
#include <float.h>

// ---------------------------------------------------------------------------
// ConvKAN3D fused pipeline, R2:
//  - fma.rn.f32x2 packed math (pairs = maxpool-x-adjacent conv outputs)
//  - zero-padded scratch activations (no bounds checks, LDG.64 loads)
//  - block1: patch-in-registers, all 32 channels per thread
// ---------------------------------------------------------------------------

using u64 = unsigned long long;

__device__ __forceinline__ u64 pk2(float lo, float hi) {
    u64 r; asm("mov.b64 %0,{%1,%2};" : "=l"(r) : "f"(lo), "f"(hi)); return r;
}
__device__ __forceinline__ void up2(u64 v, float& lo, float& hi) {
    asm("mov.b64 {%0,%1}, %2;" : "=f"(lo), "=f"(hi) : "l"(v));
}
__device__ __forceinline__ void ffma2(u64& d, u64 a, u64 b) {
    asm("fma.rn.f32x2 %0, %1, %2, %0;" : "+l"(d) : "l"(a), "l"(b));
}
__device__ __forceinline__ u64 midp(u64 A, u64 B) {
    float al, ah, bl, bh; up2(A, al, ah); up2(B, bl, bh); return pk2(ah, bl);
}

// Padded scratch (zero-initialized device globals; halos never written).
__device__ __align__(16) float g_xp [2u * 66u * 66u * 66u];          // 2.3 MB
__device__ __align__(16) float g_s1p[2u * 32u * 34u * 34u * 34u];    // 10 MB
__device__ __align__(16) float g_s2p[2u * 64u * 18u * 18u * 18u];    // 3 MB
__device__ __align__(16) float g_s3 [2u * 128u * 512u];              // 0.5 MB
__device__ float4 g_coef[224 * 11];
__device__ float  g_mean[2 * 128];

// --- piecewise cubic coefficients (prefix sums of relu(y-t)^3 expansion) ---
__global__ void coef_kernel(const float* __restrict__ k1, const float* __restrict__ sw1,
                            const float* __restrict__ k2, const float* __restrict__ sw2,
                            const float* __restrict__ k3, const float* __restrict__ sw3)
{
    const int t = threadIdx.x;
    if (t >= 224) return;
    const float* kn; const float* sw;
    if (t < 32)       { kn = k1; sw = sw1 + t * 10; }
    else if (t < 96)  { kn = k2; sw = sw2 + (t - 32) * 10; }
    else              { kn = k3; sw = sw3 + (t - 96) * 10; }

    float4 a = make_float4(0.f, 0.f, 0.f, 0.f);
    g_coef[t * 11 + 0] = a;
    for (int e = 1; e <= 10; ++e) {
        const float tk = kn[e - 1];
        const float s  = sw[e - 1];
        a.x = fmaf(-s * tk * tk, tk, a.x);
        a.y = fmaf(3.f * s * tk, tk, a.y);
        a.z = fmaf(-3.f * s, tk, a.z);
        a.w += s;
        g_coef[t * 11 + e] = a;
    }
}

// --- copy x into padded buffer ---------------------------------------------
__global__ void pad_x_kernel(const float* __restrict__ x)
{
    const int idx = blockIdx.x * blockDim.x + threadIdx.x;   // 2*64^3
    if (idx >= 2 * 262144) return;
    const int ix = idx & 63, iy = (idx >> 6) & 63, iz = (idx >> 12) & 63;
    const int b  = idx >> 18;
    g_xp[(((size_t)b * 66 + iz + 1) * 66 + iy + 1) * 66 + ix + 1] = x[idx];
}

// --- pointwise epilogue helper ---------------------------------------------
__device__ __forceinline__ float pointwise(float y, const float4* coef,
                                           float w1, float w2, float scale, float beta)
{
    int e = __float2int_rd((y + 1.0f) * 4.5f) + 1;
    e = max(0, min(10, e));
    const float4 cf = coef[e];
    const float sp  = fmaf(fmaf(fmaf(cf.w, y, cf.z), y, cf.y), y, cf.x);
    const float sig = 1.0f / (1.0f + __expf(-y));
    return fmaf(w1 * sp + w2 * (y * sig), scale, beta);
}

// --- Block 1: CIN=1, all 32 channels per thread -----------------------------
__global__ void __launch_bounds__(128)
block1_kernel(const float* __restrict__ cw,   // [32,1,27]
              const float* __restrict__ cb,
              const float* __restrict__ w1p, const float* __restrict__ w2p,
              const float* __restrict__ gp,  const float* __restrict__ bp,
              float* __restrict__ out)        // padded [2,32,34^3]
{
    constexpr int D = 64, Din = 66, P = 32, Pq = 34;

    __shared__ float  s_w[32 * 27];
    __shared__ float4 s_coef[32 * 11];
    __shared__ float  s_bias[32], s_w1[32], s_w2[32], s_scale[32], s_beta[32];

    for (int i = threadIdx.x; i < 32 * 27; i += 128) s_w[i] = cw[i];
    for (int i = threadIdx.x; i < 32 * 11; i += 128) s_coef[i] = g_coef[i];
    if (threadIdx.x < 32) {
        const int c = threadIdx.x;
        s_bias[c]  = cb[c];  s_w1[c] = w1p[c];  s_w2[c] = w2p[c];
        s_scale[c] = gp[c] * rsqrtf(1.0f + 1e-5f);  s_beta[c] = bp[c];
    }
    __syncthreads();

    const int vox = blockIdx.x * 128 + threadIdx.x;   // 0..32767
    const int b   = blockIdx.z;
    const int px = vox % P, py = (vox / P) % P, pz = vox / (P * P);

    const u64* inb = (const u64*)(g_xp + (size_t)b * Din * Din * Din);
    const int ib2  = (((2 * pz) * Din + 2 * py) * Din + 2 * px) >> 1;

    u64 A[16], Bv[16], M[16];
    #pragma unroll
    for (int a = 0; a < 4; ++a)
        #pragma unroll
        for (int r = 0; r < 4; ++r) {
            const int o = ib2 + ((((a)*Din + r) * Din) >> 1);
            A[a * 4 + r]  = inb[o];
            Bv[a * 4 + r] = inb[o + 1];
        }
    #pragma unroll
    for (int i = 0; i < 16; ++i) M[i] = midp(A[i], Bv[i]);

    #pragma unroll 1
    for (int c = 0; c < 32; ++c) {
        const float bi = s_bias[c];
        u64 acc[4];
        #pragma unroll
        for (int j = 0; j < 4; ++j) acc[j] = pk2(bi, bi);

        const float* wp = s_w + c * 27;
        #pragma unroll
        for (int tap = 0; tap < 27; ++tap) {
            const int kd = tap / 9, kh = (tap / 3) % 3, kw = tap % 3;
            const float w = wp[tap];
            const u64 ww = pk2(w, w);
            #pragma unroll
            for (int dz = 0; dz < 2; ++dz)
                #pragma unroll
                for (int dy = 0; dy < 2; ++dy) {
                    const int ri = (dz + kd) * 4 + dy + kh;
                    const u64 src = (kw == 0) ? A[ri] : (kw == 2) ? Bv[ri] : M[ri];
                    ffma2(acc[dz * 2 + dy], ww, src);
                }
        }

        float mv = -FLT_MAX;
        #pragma unroll
        for (int j = 0; j < 4; ++j) {
            float y0, y1; up2(acc[j], y0, y1);
            mv = fmaxf(mv, pointwise(y0, s_coef + c * 11, s_w1[c], s_w2[c], s_scale[c], s_beta[c]));
            mv = fmaxf(mv, pointwise(y1, s_coef + c * 11, s_w1[c], s_w2[c], s_scale[c], s_beta[c]));
        }
        out[((((size_t)b * 32 + c) * Pq + pz + 1) * Pq + py + 1) * Pq + px + 1] = mv;
    }
}

// --- Generic fused block (blocks 2 & 3) -------------------------------------
template<int CIN, int D, int CTILE, int COUT, bool PADOUT>
__global__ void __launch_bounds__(128)
conv_block(const float* __restrict__ in,     // padded [2,CIN,(D+2)^3]
           const float* __restrict__ cw,     // [COUT,CIN,27]
           const float* __restrict__ cb,
           const float* __restrict__ w1p, const float* __restrict__ w2p,
           const float* __restrict__ gp,  const float* __restrict__ bp,
           float* __restrict__ out, int coefBase)
{
    constexpr int Din = D + 2;
    constexpr int P = D / 2, Pq = P + 2, NV = P * P * P;

    const int cobase = blockIdx.y * CTILE;
    const int b      = blockIdx.z;

    __shared__ float  s_w[CIN * 27 * CTILE];   // [ci][tap][t]
    __shared__ float4 s_coef[CTILE * 11];
    __shared__ float  s_bias[CTILE], s_w1[CTILE], s_w2[CTILE],
                      s_scale[CTILE], s_beta[CTILE];

    for (int i = threadIdx.x; i < CIN * 27 * CTILE; i += 128) {
        const int t   = i % CTILE;
        const int tap = (i / CTILE) % 27;
        const int ci  = i / (CTILE * 27);
        s_w[i] = cw[((size_t)(cobase + t) * CIN + ci) * 27 + tap];
    }
    for (int i = threadIdx.x; i < CTILE * 11; i += 128)
        s_coef[i] = g_coef[(coefBase + cobase) * 11 + i];
    if (threadIdx.x < CTILE) {
        const int c = cobase + threadIdx.x;
        s_bias[threadIdx.x]  = cb[c];
        s_w1[threadIdx.x]    = w1p[c];
        s_w2[threadIdx.x]    = w2p[c];
        s_scale[threadIdx.x] = gp[c] * rsqrtf(1.0f + 1e-5f);
        s_beta[threadIdx.x]  = bp[c];
    }
    __syncthreads();

    const int vox = blockIdx.x * 128 + threadIdx.x;
    const int px = vox % P, py = (vox / P) % P, pz = vox / (P * P);

    u64 acc[CTILE][4];
    #pragma unroll
    for (int t = 0; t < CTILE; ++t) {
        const float bi = s_bias[t];
        const u64 bb = pk2(bi, bi);
        #pragma unroll
        for (int j = 0; j < 4; ++j) acc[t][j] = bb;
    }

    const u64* inb = (const u64*)(in + (size_t)b * CIN * Din * Din * Din);
    int ib2 = (((2 * pz) * Din + 2 * py) * Din + 2 * px) >> 1;

    #pragma unroll 1
    for (int ci = 0; ci < CIN; ++ci) {
        u64 A[16], Bv[16], M[16];
        #pragma unroll
        for (int a = 0; a < 4; ++a)
            #pragma unroll
            for (int r = 0; r < 4; ++r) {
                const int o = ib2 + (((a * Din + r) * Din) >> 1);
                A[a * 4 + r]  = inb[o];
                Bv[a * 4 + r] = inb[o + 1];
            }
        #pragma unroll
        for (int i = 0; i < 16; ++i) M[i] = midp(A[i], Bv[i]);

        const float* wp = s_w + ci * 27 * CTILE;
        #pragma unroll
        for (int tap = 0; tap < 27; ++tap) {
            const int kd = tap / 9, kh = (tap / 3) % 3, kw = tap % 3;
            const float4 wv = *(const float4*)(wp + tap * CTILE);  // CTILE==4
            #pragma unroll
            for (int t = 0; t < CTILE; ++t) {
                const float w = (t == 0) ? wv.x : (t == 1) ? wv.y : (t == 2) ? wv.z : wv.w;
                const u64 ww = pk2(w, w);
                #pragma unroll
                for (int dz = 0; dz < 2; ++dz)
                    #pragma unroll
                    for (int dy = 0; dy < 2; ++dy) {
                        const int ri = (dz + kd) * 4 + dy + kh;
                        const u64 src = (kw == 0) ? A[ri] : (kw == 2) ? Bv[ri] : M[ri];
                        ffma2(acc[t][dz * 2 + dy], ww, src);
                    }
            }
        }
        ib2 += (Din * Din * Din) >> 1;
    }

    #pragma unroll
    for (int t = 0; t < CTILE; ++t) {
        float mv = -FLT_MAX;
        #pragma unroll
        for (int j = 0; j < 4; ++j) {
            float y0, y1; up2(acc[t][j], y0, y1);
            mv = fmaxf(mv, pointwise(y0, s_coef + t * 11, s_w1[t], s_w2[t], s_scale[t], s_beta[t]));
            mv = fmaxf(mv, pointwise(y1, s_coef + t * 11, s_w1[t], s_w2[t], s_scale[t], s_beta[t]));
        }
        const int c = cobase + t;
        if (PADOUT)
            out[((((size_t)b * COUT + c) * Pq + pz + 1) * Pq + py + 1) * Pq + px + 1] = mv;
        else
            out[((size_t)b * COUT + c) * NV + vox] = mv;
    }
}

// --- Head -------------------------------------------------------------------
__global__ void __launch_bounds__(64)
mean_kernel(const float* __restrict__ s3)
{
    const int bc = blockIdx.x;
    const int t  = threadIdx.x;
    const float* p = s3 + (size_t)bc * 512;

    float s = 0.0f;
    #pragma unroll
    for (int i = 0; i < 8; ++i) s += p[t + i * 64];
    #pragma unroll
    for (int off = 16; off > 0; off >>= 1)
        s += __shfl_down_sync(0xffffffffu, s, off);
    __shared__ float part[2];
    if ((t & 31) == 0) part[t >> 5] = s;
    __syncthreads();
    if (t == 0) g_mean[bc] = (part[0] + part[1]) * (1.0f / 512.0f);
}

__global__ void __launch_bounds__(256)
fc_kernel(const float* __restrict__ fc1w, const float* __restrict__ fc1b,
          const float* __restrict__ fc2w, const float* __restrict__ fc2b,
          float* __restrict__ out)
{
    const int t = threadIdx.x;
    __shared__ float m[2][128];
    __shared__ float h[2][256];

    if (t < 128) { m[0][t] = g_mean[t]; m[1][t] = g_mean[128 + t]; }
    __syncthreads();

    #pragma unroll
    for (int b = 0; b < 2; ++b) {
        float s = fc1b[t];
        const float* w = fc1w + t * 128;
        #pragma unroll 8
        for (int k = 0; k < 128; ++k) s = fmaf(m[b][k], w[k], s);
        h[b][t] = fmaxf(s, 0.0f);
    }
    __syncthreads();

    if (t < 4) {
        const int b = t >> 1, o = t & 1;
        float s = fc2b[o];
        const float* w = fc2w + o * 256;
        #pragma unroll 8
        for (int k = 0; k < 256; ++k) s = fmaf(h[b][k], w[k], s);
        out[b * 2 + o] = s;
    }
}

extern "C" void kernel_launch(void* const* d_in, const int* in_sizes, int n_in,
                              void* d_out, int out_size)
{
    (void)in_sizes; (void)n_in; (void)out_size;

    const float* x     = (const float*)d_in[0];
    const float* c1_w  = (const float*)d_in[1];
    const float* c1_b  = (const float*)d_in[2];
    const float* c1_k  = (const float*)d_in[3];
    const float* c1_sw = (const float*)d_in[4];
    const float* c1_w1 = (const float*)d_in[5];
    const float* c1_w2 = (const float*)d_in[6];
    const float* bn1_g = (const float*)d_in[7];
    const float* bn1_b = (const float*)d_in[8];
    const float* c2_w  = (const float*)d_in[9];
    const float* c2_b  = (const float*)d_in[10];
    const float* c2_k  = (const float*)d_in[11];
    const float* c2_sw = (const float*)d_in[12];
    const float* c2_w1 = (const float*)d_in[13];
    const float* c2_w2 = (const float*)d_in[14];
    const float* bn2_g = (const float*)d_in[15];
    const float* bn2_b = (const float*)d_in[16];
    const float* c3_w  = (const float*)d_in[17];
    const float* c3_b  = (const float*)d_in[18];
    const float* c3_k  = (const float*)d_in[19];
    const float* c3_sw = (const float*)d_in[20];
    const float* c3_w1 = (const float*)d_in[21];
    const float* c3_w2 = (const float*)d_in[22];
    const float* bn3_g = (const float*)d_in[23];
    const float* bn3_b = (const float*)d_in[24];
    const float* fc1_w = (const float*)d_in[25];
    const float* fc1_b = (const float*)d_in[26];
    const float* fc2_w = (const float*)d_in[27];
    const float* fc2_b = (const float*)d_in[28];
    float* out = (float*)d_out;

    float *s1p, *s2p, *s3;
    cudaGetSymbolAddress((void**)&s1p, g_s1p);
    cudaGetSymbolAddress((void**)&s2p, g_s2p);
    cudaGetSymbolAddress((void**)&s3,  g_s3);

    coef_kernel<<<1, 224>>>(c1_k, c1_sw, c2_k, c2_sw, c3_k, c3_sw);
    pad_x_kernel<<<(2 * 262144 + 255) / 256, 256>>>(x);

    // Block 1: CIN=1, D=64 -> padded s1p
    block1_kernel<<<dim3(32768 / 128, 1, 2), 128>>>(
        c1_w, c1_b, c1_w1, c1_w2, bn1_g, bn1_b, s1p);

    // Block 2: CIN=32, D=32, COUT=64 -> padded s2p
    conv_block<32, 32, 4, 64, true><<<dim3(4096 / 128, 64 / 4, 2), 128>>>(
        s1p, c2_w, c2_b, c2_w1, c2_w2, bn2_g, bn2_b, s2p, 32);

    // Block 3: CIN=64, D=16, COUT=128 -> unpadded s3
    conv_block<64, 16, 4, 128, false><<<dim3(512 / 128, 128 / 4, 2), 128>>>(
        s2p, c3_w, c3_b, c3_w1, c3_w2, bn3_g, bn3_b, s3, 96);

    mean_kernel<<<256, 64>>>(s3);
    fc_kernel<<<1, 256>>>(fc1_w, fc1_b, fc2_w, fc2_b, out);
}